// round 2
// baseline (speedup 1.0000x reference)
#include <cuda_runtime.h>
#include <cstdint>

// ---------------- problem constants ----------------
#define Bn 64
#define Ln 32
#define Dn 768
#define TDn 768
#define Tn 63
#define Sn 32
#define OUTW (Dn + 2 * Tn) // 894

#define K1 3072
#define N1 3072
#define K2 2304
#define N2 3840
#define KSPL1 3
#define KS1 1024
#define KSPL2 2
#define KS2 1152

// ---------------- device globals (scratch; no allocation allowed) ----------------
__device__ float g_W1[K1 * N1];          // tf32-rounded [W_buf;W_s1;W_s2;W_lat]
__device__ float g_W2[K2 * N2];          // tf32-rounded [W_left;W_right;W_track]
__device__ float g_A1[Bn * K1];          // [bh | s1h | s2h | trk_h_prev] (tf32-rounded)
__device__ float g_A2[Bn * K2];          // [s2h | s1h | trk_h_new]
__device__ float g_C1[KSPL1 * Bn * N1];  // GEMM1 split-K partials
__device__ float g_C2[KSPL2 * Bn * N2];  // GEMM2 split-K partials
__device__ float g_sh[Bn * Sn * Dn];     // stack_h
__device__ float g_sc[Bn * Sn * Dn];     // stack_c
__device__ float g_trkc[Bn * TDn];
__device__ int g_bufpos[Tn * Bn];
__device__ int g_p1[Tn * Bn];
__device__ int g_p2[Tn * Bn];
__device__ int g_wpos[Tn * Bn];
__device__ int g_op[Tn * Bn];
__device__ int g_fpos[Bn];

// ---------------- helpers ----------------
__device__ __forceinline__ float to_tf32(float x) {
    uint32_t y;
    asm("cvt.rna.tf32.f32 %0, %1;" : "=r"(y) : "f"(x));
    return __uint_as_float(y);
}
__device__ __forceinline__ float sigm(float x) { return 1.f / (1.f + expf(-x)); }

// ---------------- prologue: precompute shift/reduce indices ----------------
__global__ void idx_kernel(const int* __restrict__ tr) {
    int b = threadIdx.x;
    if (b >= Bn) return;
    int ptr = 0, buft = 0;
    for (int t = 0; t < Tn; t++) {
        int op = tr[b * Tn + t];
        int bp = Ln - 1 - buft;
        bp = bp < 0 ? 0 : (bp > Ln - 1 ? Ln - 1 : bp);
        g_bufpos[t * Bn + b] = bp;
        g_p1[t * Bn + b] = (ptr > 0) ? min(ptr - 1, Sn - 1) : -1;
        g_p2[t * Bn + b] = (ptr > 1) ? min(ptr - 2, Sn - 1) : -1;
        int wp = (op == 0) ? ptr : ptr - 2;
        wp = wp < 0 ? 0 : (wp > Sn - 1 ? Sn - 1 : wp);
        g_wpos[t * Bn + b] = wp;
        g_op[t * Bn + b] = op;
        ptr += (op == 0) ? 1 : ((op == 1) ? -1 : 0);
        buft += (op == 0) ? 1 : 0;
    }
    int fp = ptr - 1;
    fp = fp < 0 ? 0 : (fp > Sn - 1 ? Sn - 1 : fp);
    g_fpos[b] = fp;
}

// ---------------- prologue: concat + tf32-round weights ----------------
__global__ void conv_w(const float* __restrict__ Wbuf, const float* __restrict__ Ws1,
                       const float* __restrict__ Ws2, const float* __restrict__ Wlat,
                       const float* __restrict__ Wl, const float* __restrict__ Wr,
                       const float* __restrict__ Wt) {
    const int total1 = K1 * N1;
    const int total2 = K2 * N2;
    for (int i = blockIdx.x * blockDim.x + threadIdx.x; i < total1 + total2;
         i += gridDim.x * blockDim.x) {
        if (i < total1) {
            int k = i / N1, n = i - k * N1;
            const float* src = (k < 768) ? Wbuf : (k < 1536) ? Ws1 : (k < 2304) ? Ws2 : Wlat;
            g_W1[i] = to_tf32(src[(k % 768) * N1 + n]);
        } else {
            int j = i - total1;
            int k = j / N2, n = j - k * N2;
            const float* src = (k < 768) ? Wl : (k < 1536) ? Wr : Wt;
            g_W2[j] = to_tf32(src[(k % 768) * N2 + n]);
        }
    }
}

// ---------------- prologue: zero state + build A1/A2 for step 0 ----------------
__global__ void init_kernel(const float* __restrict__ buffer_h) {
    const int n1 = Bn * Sn * Dn;
    const int n2 = 2 * n1;
    const int n3 = n2 + Bn * TDn;
    const int n4 = n3 + Bn * K1;
    const int n5 = n4 + Bn * K2;
    for (int i = blockIdx.x * blockDim.x + threadIdx.x; i < n5; i += gridDim.x * blockDim.x) {
        if (i < n1) g_sh[i] = 0.f;
        else if (i < n2) g_sc[i - n1] = 0.f;
        else if (i < n3) g_trkc[i - n2] = 0.f;
        else if (i < n4) {
            int j = i - n3;
            int b = j / K1, k = j - b * K1;
            // step 0: buf_t=0 -> buf_pos = L-1 = 31; stack empty -> s1h=s2h=0; trk_h=0
            g_A1[j] = (k < 768) ? to_tf32(buffer_h[b * Ln * Dn + (Ln - 1) * Dn + k]) : 0.f;
        } else {
            g_A2[i - n4] = 0.f;
        }
    }
}

// ---------------- split-K TF32 GEMM: C[ky][64][N] = A[64, ks] @ W[ks, N] ----------------
#define BM 64
#define BN 64
#define BK 64
#define SST 68 // padded smem stride (floats)

__device__ __forceinline__ void cp16(uint32_t dst, const void* src) {
    asm volatile("cp.async.cg.shared.global [%0], [%1], 16;" :: "r"(dst), "l"(src));
}

__global__ void __launch_bounds__(256) gemm_tf32(int which) {
    const float* A;
    const float* W;
    float* C;
    int ldA, N, KS;
    if (which == 1) { A = g_A1; W = g_W1; C = g_C1; ldA = K1; N = N1; KS = KS1; }
    else            { A = g_A2; W = g_W2; C = g_C2; ldA = K2; N = N2; KS = KS2; }

    extern __shared__ float sm[];
    float* Asb[2] = { sm, sm + BM * SST };
    float* Wsb[2] = { sm + 2 * BM * SST, sm + 3 * BM * SST };

    const int tid = threadIdx.x;
    const int n0 = blockIdx.x * BN;
    const int kbase0 = blockIdx.y * KS;
    const int niter = KS / BK;

    const int lane = tid & 31, w = tid >> 5;
    const int wm = w >> 1, wn = w & 1;
    const int g = lane >> 2, tg = lane & 3;

    float acc[4][4];
#pragma unroll
    for (int i = 0; i < 4; i++)
#pragma unroll
        for (int j = 0; j < 4; j++) acc[i][j] = 0.f;

    // prefetch tile 0
    {
        float* as = Asb[0];
        float* ws = Wsb[0];
#pragma unroll
        for (int j = 0; j < 4; j++) {
            int idx = tid + j * 256;
            int r = idx >> 4;
            int c = (idx & 15) << 2;
            cp16((uint32_t)__cvta_generic_to_shared(as + r * SST + c), A + r * ldA + kbase0 + c);
            cp16((uint32_t)__cvta_generic_to_shared(ws + r * SST + c), W + (size_t)(kbase0 + r) * N + n0 + c);
        }
        asm volatile("cp.async.commit_group;");
    }

    for (int it = 0; it < niter; ++it) {
        if (it + 1 < niter) {
            int kb = kbase0 + (it + 1) * BK;
            float* as = Asb[(it + 1) & 1];
            float* ws = Wsb[(it + 1) & 1];
#pragma unroll
            for (int j = 0; j < 4; j++) {
                int idx = tid + j * 256;
                int r = idx >> 4;
                int c = (idx & 15) << 2;
                cp16((uint32_t)__cvta_generic_to_shared(as + r * SST + c), A + r * ldA + kb + c);
                cp16((uint32_t)__cvta_generic_to_shared(ws + r * SST + c), W + (size_t)(kb + r) * N + n0 + c);
            }
            asm volatile("cp.async.commit_group;");
            asm volatile("cp.async.wait_group 1;");
        } else {
            asm volatile("cp.async.wait_group 0;");
        }
        __syncthreads();

        const float* as = Asb[it & 1] + wm * 16 * SST;
        const float* ws = Wsb[it & 1] + wn * 32;
#pragma unroll
        for (int ks = 0; ks < 8; ks++) {
            int kk = ks * 8;
            uint32_t a0 = __float_as_uint(as[g * SST + kk + tg]);
            uint32_t a1 = __float_as_uint(as[(g + 8) * SST + kk + tg]);
            uint32_t a2 = __float_as_uint(as[g * SST + kk + tg + 4]);
            uint32_t a3 = __float_as_uint(as[(g + 8) * SST + kk + tg + 4]);
            const float* wk = ws + kk * SST;
#pragma unroll
            for (int nt = 0; nt < 4; nt++) {
                uint32_t b0 = __float_as_uint(wk[tg * SST + nt * 8 + g]);
                uint32_t b1 = __float_as_uint(wk[(tg + 4) * SST + nt * 8 + g]);
                asm volatile(
                    "mma.sync.aligned.m16n8k8.row.col.f32.tf32.tf32.f32 "
                    "{%0,%1,%2,%3}, {%4,%5,%6,%7}, {%8,%9}, {%0,%1,%2,%3};"
                    : "+f"(acc[nt][0]), "+f"(acc[nt][1]), "+f"(acc[nt][2]), "+f"(acc[nt][3])
                    : "r"(a0), "r"(a1), "r"(a2), "r"(a3), "r"(b0), "r"(b1));
            }
        }
        __syncthreads();
    }

    // epilogue: write split-K partial (exclusive per block -> plain stores)
    float* Cp = C + (size_t)blockIdx.y * (Bn * N) + n0;
    int row0 = wm * 16 + g;
#pragma unroll
    for (int nt = 0; nt < 4; nt++) {
        int col = wn * 32 + nt * 8 + tg * 2;
        *(float2*)(Cp + (size_t)row0 * N + col) = make_float2(acc[nt][0], acc[nt][1]);
        *(float2*)(Cp + (size_t)(row0 + 8) * N + col) = make_float2(acc[nt][2], acc[nt][3]);
    }
}

// ---------------- per-step: tracker LSTM update + logits ----------------
__global__ void tracker_kernel(int t, const float* __restrict__ b_lat,
                               const float* __restrict__ Wtr, const float* __restrict__ btr,
                               float* __restrict__ out) {
    int b = blockIdx.x;
    int d = threadIdx.x;
    const float* c0 = g_C1 + (size_t)b * N1;
    const float* c1 = g_C1 + (size_t)Bn * N1 + (size_t)b * N1;
    const float* c2 = g_C1 + (size_t)2 * Bn * N1 + (size_t)b * N1;
    float a  = c0[d]        + c1[d]        + c2[d]        + b_lat[d];
    float ii = c0[d + 768]  + c1[d + 768]  + c2[d + 768]  + b_lat[d + 768];
    float ff = c0[d + 1536] + c1[d + 1536] + c2[d + 1536] + b_lat[d + 1536];
    float oo = c0[d + 2304] + c1[d + 2304] + c2[d + 2304] + b_lat[d + 2304];
    float c = tanhf(a) * sigm(ii) + sigm(ff) * g_trkc[b * TDn + d];
    float h = sigm(oo) * tanhf(c);
    g_trkc[b * TDn + d] = c;
    float hr = to_tf32(h);
    g_A2[b * K2 + 1536 + d] = hr; // trk_h slice for this step's GEMM2
    g_A1[b * K1 + 2304 + d] = hr; // trk_h slice for next step's GEMM1

    // logits = h @ W_trans + b_trans   (block reduce over d)
    float l0 = h * Wtr[d * 2];
    float l1 = h * Wtr[d * 2 + 1];
#pragma unroll
    for (int off = 16; off; off >>= 1) {
        l0 += __shfl_down_sync(0xffffffffu, l0, off);
        l1 += __shfl_down_sync(0xffffffffu, l1, off);
    }
    __shared__ float red[24][2];
    int wid = d >> 5;
    if ((d & 31) == 0) { red[wid][0] = l0; red[wid][1] = l1; }
    __syncthreads();
    if (d < 32) {
        float r0 = (d < 24) ? red[d][0] : 0.f;
        float r1 = (d < 24) ? red[d][1] : 0.f;
#pragma unroll
        for (int off = 16; off; off >>= 1) {
            r0 += __shfl_down_sync(0xffffffffu, r0, off);
            r1 += __shfl_down_sync(0xffffffffu, r1, off);
        }
        if (d == 0) {
            out[(size_t)b * OUTW + Dn + 2 * t]     = r0 + btr[0];
            out[(size_t)b * OUTW + Dn + 2 * t + 1] = r1 + btr[1];
        }
    }
}

// ---------------- per-step: compose + stack update + next-step gather ----------------
__global__ void compose_kernel(int t, const float* __restrict__ buffer_h,
                               const float* __restrict__ buffer_c,
                               const float* __restrict__ b_left) {
    int b = blockIdx.x;
    int d = threadIdx.x;
    int base = t * Bn + b;
    int p1 = g_p1[base], p2 = g_p2[base], wp = g_wpos[base], op = g_op[base], bp = g_bufpos[base];

    // thread (b,d) only ever touches stack[(b, *, d)] -> no cross-thread hazards
    float s1c = (p1 >= 0) ? g_sc[(b * Sn + p1) * Dn + d] : 0.f;
    float s2c = (p2 >= 0) ? g_sc[(b * Sn + p2) * Dn + d] : 0.f;

    const float* c0 = g_C2 + (size_t)b * N2;
    const float* c1 = g_C2 + (size_t)Bn * N2 + (size_t)b * N2;
    float gi  = c0[d]         + c1[d]         + b_left[d];
    float gfl = c0[d + 768]   + c1[d + 768]   + b_left[d + 768];
    float gfr = c0[d + 1536]  + c1[d + 1536]  + b_left[d + 1536];
    float go  = c0[d + 2304]  + c1[d + 2304]  + b_left[d + 2304];
    float gg  = c0[d + 3072]  + c1[d + 3072]  + b_left[d + 3072];

    float cc = sigm(gfl) * s2c + sigm(gfr) * s1c + sigm(gi) * tanhf(gg);
    float ch = sigm(go) * tanhf(cc);

    float wh, wc;
    if (op == 0) {
        wh = buffer_h[(b * Ln + bp) * Dn + d];
        wc = buffer_c[(b * Ln + bp) * Dn + d];
    } else if (op == 1) {
        wh = ch; wc = cc;
    } else {
        wh = g_sh[(b * Sn + wp) * Dn + d];
        wc = g_sc[(b * Sn + wp) * Dn + d];
    }
    g_sh[(b * Sn + wp) * Dn + d] = wh;
    g_sc[(b * Sn + wp) * Dn + d] = wc;

    if (t + 1 < Tn) {
        int nb = (t + 1) * Bn + b;
        int nbp = g_bufpos[nb], np1 = g_p1[nb], np2 = g_p2[nb];
        float nbh = to_tf32(buffer_h[(b * Ln + nbp) * Dn + d]);
        float ns1 = (np1 >= 0) ? to_tf32(g_sh[(b * Sn + np1) * Dn + d]) : 0.f;
        float ns2 = (np2 >= 0) ? to_tf32(g_sh[(b * Sn + np2) * Dn + d]) : 0.f;
        g_A1[b * K1 + d] = nbh;
        g_A1[b * K1 + 768 + d] = ns1;
        g_A1[b * K1 + 1536 + d] = ns2;
        g_A2[b * K2 + d] = ns2;       // s2h first for W_left
        g_A2[b * K2 + 768 + d] = ns1; // s1h for W_right
    }
}

// ---------------- epilogue: final_h ----------------
__global__ void final_kernel(float* __restrict__ out) {
    int b = blockIdx.x, d = threadIdx.x;
    out[(size_t)b * OUTW + d] = g_sh[(b * Sn + g_fpos[b]) * Dn + d];
}

// ---------------- launch ----------------
extern "C" void kernel_launch(void* const* d_in, const int* in_sizes, int n_in,
                              void* d_out, int out_size) {
    const float* buffer_h = (const float*)d_in[0];
    const float* buffer_c = (const float*)d_in[1];
    const int* transitions = (const int*)d_in[2];
    const float* W_buf  = (const float*)d_in[3];
    const float* W_s1   = (const float*)d_in[4];
    const float* W_s2   = (const float*)d_in[5];
    const float* W_lat  = (const float*)d_in[6];
    const float* b_lat  = (const float*)d_in[7];
    const float* W_trans = (const float*)d_in[8];
    const float* b_trans = (const float*)d_in[9];
    const float* W_left = (const float*)d_in[10];
    const float* b_left = (const float*)d_in[11];
    const float* W_right = (const float*)d_in[12];
    const float* W_track = (const float*)d_in[13];
    float* out = (float*)d_out;

    const size_t smem = 4 * BM * SST * sizeof(float); // 69632 B
    cudaFuncSetAttribute(gemm_tf32, cudaFuncAttributeMaxDynamicSharedMemorySize, (int)smem);

    conv_w<<<1024, 256>>>(W_buf, W_s1, W_s2, W_lat, W_left, W_right, W_track);
    idx_kernel<<<1, 64>>>(transitions);
    init_kernel<<<512, 256>>>(buffer_h);

    for (int t = 0; t < Tn; t++) {
        gemm_tf32<<<dim3(N1 / BN, KSPL1), 256, smem>>>(1);
        tracker_kernel<<<Bn, Dn>>>(t, b_lat, W_trans, b_trans, out);
        gemm_tf32<<<dim3(N2 / BN, KSPL2), 256, smem>>>(2);
        compose_kernel<<<Bn, Dn>>>(t, buffer_h, buffer_c, b_left);
    }
    final_kernel<<<Bn, Dn>>>(out);
}

// round 4
// speedup vs baseline: 1.0500x; 1.0500x over previous
#include <cuda_runtime.h>
#include <cstdint>

// ---------------- problem constants ----------------
#define Bn 64
#define Ln 32
#define Dn 768
#define TDn 768
#define Tn 63
#define Sn 32
#define OUTW (Dn + 2 * Tn) // 894

#define K1 3072
#define N1 3072
#define K2 2304
#define N2 3840
#define KSPL1 6
#define KS1 512
#define KSPL2 4
#define KS2 576

// ---------------- device globals (scratch; no allocation allowed) ----------------
__device__ float g_W1[K1 * N1];          // tf32-rounded [W_buf;W_s1;W_s2;W_lat]
__device__ float g_W2[K2 * N2];          // tf32-rounded [W_left;W_right;W_track]
__device__ float g_A1[Bn * K1];          // [bh | s1h | s2h | trk_h_prev] (tf32-rounded)
__device__ float g_A2[Bn * K2];          // [s2h | s1h | trk_h_new]
__device__ float g_C1[KSPL1 * Bn * N1];  // GEMM1 split-K partials
__device__ float g_C2[KSPL2 * Bn * N2];  // GEMM2 split-K partials
__device__ float g_sh[Bn * Sn * Dn];     // stack_h
__device__ float g_sc[Bn * Sn * Dn];     // stack_c
__device__ float g_trkc[Bn * TDn];
__device__ int g_bufpos[Tn * Bn];
__device__ int g_p1[Tn * Bn];
__device__ int g_p2[Tn * Bn];
__device__ int g_wpos[Tn * Bn];
__device__ int g_op[Tn * Bn];
__device__ int g_fpos[Bn];

// ---------------- helpers ----------------
__device__ __forceinline__ float to_tf32(float x) {
    uint32_t y;
    asm("cvt.rna.tf32.f32 %0, %1;" : "=r"(y) : "f"(x));
    return __uint_as_float(y);
}
__device__ __forceinline__ float sigm(float x) { return 1.f / (1.f + expf(-x)); }

// ---------------- prologue: precompute shift/reduce indices ----------------
__global__ void idx_kernel(const int* __restrict__ tr) {
    int b = threadIdx.x;
    if (b >= Bn) return;
    int ptr = 0, buft = 0;
    for (int t = 0; t < Tn; t++) {
        int op = tr[b * Tn + t];
        int bp = Ln - 1 - buft;
        bp = bp < 0 ? 0 : (bp > Ln - 1 ? Ln - 1 : bp);
        g_bufpos[t * Bn + b] = bp;
        g_p1[t * Bn + b] = (ptr > 0) ? min(ptr - 1, Sn - 1) : -1;
        g_p2[t * Bn + b] = (ptr > 1) ? min(ptr - 2, Sn - 1) : -1;
        int wp = (op == 0) ? ptr : ptr - 2;
        wp = wp < 0 ? 0 : (wp > Sn - 1 ? Sn - 1 : wp);
        g_wpos[t * Bn + b] = wp;
        g_op[t * Bn + b] = op;
        ptr += (op == 0) ? 1 : ((op == 1) ? -1 : 0);
        buft += (op == 0) ? 1 : 0;
    }
    int fp = ptr - 1;
    fp = fp < 0 ? 0 : (fp > Sn - 1 ? Sn - 1 : fp);
    g_fpos[b] = fp;
}

// ---------------- prologue: concat + tf32-round weights ----------------
__global__ void conv_w(const float* __restrict__ Wbuf, const float* __restrict__ Ws1,
                       const float* __restrict__ Ws2, const float* __restrict__ Wlat,
                       const float* __restrict__ Wl, const float* __restrict__ Wr,
                       const float* __restrict__ Wt) {
    const int total1 = K1 * N1;
    const int total2 = K2 * N2;
    for (int i = blockIdx.x * blockDim.x + threadIdx.x; i < total1 + total2;
         i += gridDim.x * blockDim.x) {
        if (i < total1) {
            int k = i / N1, n = i - k * N1;
            const float* src = (k < 768) ? Wbuf : (k < 1536) ? Ws1 : (k < 2304) ? Ws2 : Wlat;
            g_W1[i] = to_tf32(src[(k % 768) * N1 + n]);
        } else {
            int j = i - total1;
            int k = j / N2, n = j - k * N2;
            const float* src = (k < 768) ? Wl : (k < 1536) ? Wr : Wt;
            g_W2[j] = to_tf32(src[(k % 768) * N2 + n]);
        }
    }
}

// ---------------- prologue: zero state + build A1/A2 for step 0 ----------------
__global__ void init_kernel(const float* __restrict__ buffer_h) {
    const int n1 = Bn * Sn * Dn;
    const int n2 = 2 * n1;
    const int n3 = n2 + Bn * TDn;
    const int n4 = n3 + Bn * K1;
    const int n5 = n4 + Bn * K2;
    for (int i = blockIdx.x * blockDim.x + threadIdx.x; i < n5; i += gridDim.x * blockDim.x) {
        if (i < n1) g_sh[i] = 0.f;
        else if (i < n2) g_sc[i - n1] = 0.f;
        else if (i < n3) g_trkc[i - n2] = 0.f;
        else if (i < n4) {
            int j = i - n3;
            int b = j / K1, k = j - b * K1;
            g_A1[j] = (k < 768) ? to_tf32(buffer_h[b * Ln * Dn + (Ln - 1) * Dn + k]) : 0.f;
        } else {
            g_A2[i - n4] = 0.f;
        }
    }
}

// ---------------- split-K TF32 GEMM: C[ky][64][N] = A[64, ks] @ W[ks, N] ----------------
#define BM 64
#define BN 64
#define BK 64
#define SST 68       // padded smem stride (floats)
#define NSTAGE 3
#define STG_FLT (2 * BM * SST) // floats per stage (A tile + W tile)

__device__ __forceinline__ void cp16(uint32_t dst, const void* src) {
    asm volatile("cp.async.cg.shared.global [%0], [%1], 16;" :: "r"(dst), "l"(src));
}

__global__ void __launch_bounds__(256, 2) gemm_tf32(int which) {
    const float* A;
    const float* W;
    float* C;
    int ldA, N, KS;
    if (which == 1) { A = g_A1; W = g_W1; C = g_C1; ldA = K1; N = N1; KS = KS1; }
    else            { A = g_A2; W = g_W2; C = g_C2; ldA = K2; N = N2; KS = KS2; }

    extern __shared__ float sm[];

    const int tid = threadIdx.x;
    const int n0 = blockIdx.x * BN;
    const int kbase0 = blockIdx.y * KS;
    const int niter = KS / BK;

    const int lane = tid & 31, w = tid >> 5;
    const int wm = w >> 1, wn = w & 1;
    const int g = lane >> 2, tg = lane & 3;

    float acc[4][4];
#pragma unroll
    for (int i = 0; i < 4; i++)
#pragma unroll
        for (int j = 0; j < 4; j++) acc[i][j] = 0.f;

    // prologue: prefetch stages 0..NSTAGE-2
#pragma unroll
    for (int s = 0; s < NSTAGE - 1; s++) {
        float* as = sm + s * STG_FLT;
        float* ws = as + BM * SST;
        int kb = kbase0 + s * BK;
#pragma unroll
        for (int j = 0; j < 4; j++) {
            int idx = tid + j * 256;
            int r = idx >> 4;
            int c = (idx & 15) << 2;
            cp16((uint32_t)__cvta_generic_to_shared(as + r * SST + c), A + r * ldA + kb + c);
            cp16((uint32_t)__cvta_generic_to_shared(ws + r * SST + c), W + (size_t)(kb + r) * N + n0 + c);
        }
        asm volatile("cp.async.commit_group;");
    }

    for (int it = 0; it < niter; ++it) {
        if (it + NSTAGE - 1 < niter) {
            int s = (it + NSTAGE - 1) % NSTAGE;
            float* as = sm + s * STG_FLT;
            float* ws = as + BM * SST;
            int kb = kbase0 + (it + NSTAGE - 1) * BK;
#pragma unroll
            for (int j = 0; j < 4; j++) {
                int idx = tid + j * 256;
                int r = idx >> 4;
                int c = (idx & 15) << 2;
                cp16((uint32_t)__cvta_generic_to_shared(as + r * SST + c), A + r * ldA + kb + c);
                cp16((uint32_t)__cvta_generic_to_shared(ws + r * SST + c), W + (size_t)(kb + r) * N + n0 + c);
            }
            asm volatile("cp.async.commit_group;");
            asm volatile("cp.async.wait_group %0;" :: "n"(NSTAGE - 1));
        } else {
            // tail: wait until stage `it` is complete
            int pend = niter - 1 - it;
            if (pend == 1) asm volatile("cp.async.wait_group 1;");
            else if (pend == 0) asm volatile("cp.async.wait_group 0;");
            else asm volatile("cp.async.wait_group 2;");
        }
        __syncthreads();

        const float* as = sm + (it % NSTAGE) * STG_FLT + wm * 16 * SST;
        const float* ws = sm + (it % NSTAGE) * STG_FLT + BM * SST + wn * 32;
#pragma unroll
        for (int ks = 0; ks < 8; ks++) {
            int kk = ks * 8;
            uint32_t a0 = __float_as_uint(as[g * SST + kk + tg]);
            uint32_t a1 = __float_as_uint(as[(g + 8) * SST + kk + tg]);
            uint32_t a2 = __float_as_uint(as[g * SST + kk + tg + 4]);
            uint32_t a3 = __float_as_uint(as[(g + 8) * SST + kk + tg + 4]);
            const float* wk = ws + kk * SST;
#pragma unroll
            for (int nt = 0; nt < 4; nt++) {
                uint32_t b0 = __float_as_uint(wk[tg * SST + nt * 8 + g]);
                uint32_t b1 = __float_as_uint(wk[(tg + 4) * SST + nt * 8 + g]);
                asm volatile(
                    "mma.sync.aligned.m16n8k8.row.col.f32.tf32.tf32.f32 "
                    "{%0,%1,%2,%3}, {%4,%5,%6,%7}, {%8,%9}, {%0,%1,%2,%3};"
                    : "+f"(acc[nt][0]), "+f"(acc[nt][1]), "+f"(acc[nt][2]), "+f"(acc[nt][3])
                    : "r"(a0), "r"(a1), "r"(a2), "r"(a3), "r"(b0), "r"(b1));
            }
        }
        __syncthreads();
    }

    // epilogue: write split-K partial (exclusive per block -> plain stores)
    float* Cp = C + (size_t)blockIdx.y * (Bn * N) + n0;
    int row0 = wm * 16 + g;
#pragma unroll
    for (int nt = 0; nt < 4; nt++) {
        int col = wn * 32 + nt * 8 + tg * 2;
        *(float2*)(Cp + (size_t)row0 * N + col) = make_float2(acc[nt][0], acc[nt][1]);
        *(float2*)(Cp + (size_t)(row0 + 8) * N + col) = make_float2(acc[nt][2], acc[nt][3]);
    }
}

// ---------------- per-step: tracker LSTM update + logits ----------------
__global__ void tracker_kernel(int t, const float* __restrict__ b_lat,
                               const float* __restrict__ Wtr, const float* __restrict__ btr,
                               float* __restrict__ out) {
    int b = blockIdx.x;
    int d = threadIdx.x;
    float a = b_lat[d], ii = b_lat[d + 768], ff = b_lat[d + 1536], oo = b_lat[d + 2304];
#pragma unroll
    for (int p = 0; p < KSPL1; p++) {
        const float* cp = g_C1 + (size_t)p * Bn * N1 + (size_t)b * N1;
        a  += cp[d];
        ii += cp[d + 768];
        ff += cp[d + 1536];
        oo += cp[d + 2304];
    }
    float c = tanhf(a) * sigm(ii) + sigm(ff) * g_trkc[b * TDn + d];
    float h = sigm(oo) * tanhf(c);
    g_trkc[b * TDn + d] = c;
    float hr = to_tf32(h);
    g_A2[b * K2 + 1536 + d] = hr; // trk_h slice for this step's GEMM2
    g_A1[b * K1 + 2304 + d] = hr; // trk_h slice for next step's GEMM1

    // logits = h @ W_trans + b_trans   (block reduce over d)
    float l0 = h * Wtr[d * 2];
    float l1 = h * Wtr[d * 2 + 1];
#pragma unroll
    for (int off = 16; off; off >>= 1) {
        l0 += __shfl_down_sync(0xffffffffu, l0, off);
        l1 += __shfl_down_sync(0xffffffffu, l1, off);
    }
    __shared__ float red[24][2];
    int wid = d >> 5;
    if ((d & 31) == 0) { red[wid][0] = l0; red[wid][1] = l1; }
    __syncthreads();
    if (d < 32) {
        float r0 = (d < 24) ? red[d][0] : 0.f;
        float r1 = (d < 24) ? red[d][1] : 0.f;
#pragma unroll
        for (int off = 16; off; off >>= 1) {
            r0 += __shfl_down_sync(0xffffffffu, r0, off);
            r1 += __shfl_down_sync(0xffffffffu, r1, off);
        }
        if (d == 0) {
            out[(size_t)b * OUTW + Dn + 2 * t]     = r0 + btr[0];
            out[(size_t)b * OUTW + Dn + 2 * t + 1] = r1 + btr[1];
        }
    }
}

// ---------------- per-step: compose + stack update + next-step gather ----------------
__global__ void compose_kernel(int t, const float* __restrict__ buffer_h,
                               const float* __restrict__ buffer_c,
                               const float* __restrict__ b_left) {
    int b = blockIdx.x;
    int d = threadIdx.x;
    int base = t * Bn + b;
    int p1 = g_p1[base], p2 = g_p2[base], wp = g_wpos[base], op = g_op[base], bp = g_bufpos[base];

    float s1c = (p1 >= 0) ? g_sc[(b * Sn + p1) * Dn + d] : 0.f;
    float s2c = (p2 >= 0) ? g_sc[(b * Sn + p2) * Dn + d] : 0.f;

    float gi = b_left[d], gfl = b_left[d + 768], gfr = b_left[d + 1536];
    float go = b_left[d + 2304], gg = b_left[d + 3072];
#pragma unroll
    for (int p = 0; p < KSPL2; p++) {
        const float* cp = g_C2 + (size_t)p * Bn * N2 + (size_t)b * N2;
        gi  += cp[d];
        gfl += cp[d + 768];
        gfr += cp[d + 1536];
        go  += cp[d + 2304];
        gg  += cp[d + 3072];
    }

    float cc = sigm(gfl) * s2c + sigm(gfr) * s1c + sigm(gi) * tanhf(gg);
    float ch = sigm(go) * tanhf(cc);

    float wh, wc;
    if (op == 0) {
        wh = buffer_h[(b * Ln + bp) * Dn + d];
        wc = buffer_c[(b * Ln + bp) * Dn + d];
    } else if (op == 1) {
        wh = ch; wc = cc;
    } else {
        wh = g_sh[(b * Sn + wp) * Dn + d];
        wc = g_sc[(b * Sn + wp) * Dn + d];
    }
    g_sh[(b * Sn + wp) * Dn + d] = wh;
    g_sc[(b * Sn + wp) * Dn + d] = wc;

    if (t + 1 < Tn) {
        int nb = (t + 1) * Bn + b;
        int nbp = g_bufpos[nb], np1 = g_p1[nb], np2 = g_p2[nb];
        float nbh = to_tf32(buffer_h[(b * Ln + nbp) * Dn + d]);
        float ns1 = (np1 >= 0) ? to_tf32(g_sh[(b * Sn + np1) * Dn + d]) : 0.f;
        float ns2 = (np2 >= 0) ? to_tf32(g_sh[(b * Sn + np2) * Dn + d]) : 0.f;
        g_A1[b * K1 + d] = nbh;
        g_A1[b * K1 + 768 + d] = ns1;
        g_A1[b * K1 + 1536 + d] = ns2;
        g_A2[b * K2 + d] = ns2;       // s2h first for W_left
        g_A2[b * K2 + 768 + d] = ns1; // s1h for W_right
    }
}

// ---------------- epilogue: final_h ----------------
__global__ void final_kernel(float* __restrict__ out) {
    int b = blockIdx.x, d = threadIdx.x;
    out[(size_t)b * OUTW + d] = g_sh[(b * Sn + g_fpos[b]) * Dn + d];
}

// ---------------- launch ----------------
extern "C" void kernel_launch(void* const* d_in, const int* in_sizes, int n_in,
                              void* d_out, int out_size) {
    const float* buffer_h = (const float*)d_in[0];
    const float* buffer_c = (const float*)d_in[1];
    const int* transitions = (const int*)d_in[2];
    const float* W_buf  = (const float*)d_in[3];
    const float* W_s1   = (const float*)d_in[4];
    const float* W_s2   = (const float*)d_in[5];
    const float* W_lat  = (const float*)d_in[6];
    const float* b_lat  = (const float*)d_in[7];
    const float* W_trans = (const float*)d_in[8];
    const float* b_trans = (const float*)d_in[9];
    const float* W_left = (const float*)d_in[10];
    const float* b_left = (const float*)d_in[11];
    const float* W_right = (const float*)d_in[12];
    const float* W_track = (const float*)d_in[13];
    float* out = (float*)d_out;

    const size_t smem = (size_t)NSTAGE * STG_FLT * sizeof(float); // 104448 B
    cudaFuncSetAttribute(gemm_tf32, cudaFuncAttributeMaxDynamicSharedMemorySize, (int)smem);

    conv_w<<<1024, 256>>>(W_buf, W_s1, W_s2, W_lat, W_left, W_right, W_track);
    idx_kernel<<<1, 64>>>(transitions);
    init_kernel<<<512, 256>>>(buffer_h);

    for (int t = 0; t < Tn; t++) {
        gemm_tf32<<<dim3(N1 / BN, KSPL1), 256, smem>>>(1);
        tracker_kernel<<<Bn, Dn>>>(t, b_lat, W_trans, b_trans, out);
        gemm_tf32<<<dim3(N2 / BN, KSPL2), 256, smem>>>(2);
        compose_kernel<<<Bn, Dn>>>(t, buffer_h, buffer_c, b_left);
    }
    final_kernel<<<Bn, Dn>>>(out);
}

// round 5
// speedup vs baseline: 1.3238x; 1.2608x over previous
#include <cuda_runtime.h>
#include <cstdint>

// ---------------- problem constants ----------------
#define Bn 64
#define Ln 32
#define Dn 768
#define TDn 768
#define Tn 63
#define Sn 32
#define OUTW (Dn + 2 * Tn) // 894

#define K1 3072
#define N1 3072
#define K2 2304
#define N2 3840
#define KSPL1 12
#define KS1 256
#define KSPL2 9
#define KS2 256

// ---------------- device globals ----------------
__device__ float g_W1[K1 * N1];
__device__ float g_W2[K2 * N2];
__device__ float g_A1[Bn * K1];
__device__ float g_A2[Bn * K2];
__device__ float g_C1[KSPL1 * Bn * N1];
__device__ float g_C2[KSPL2 * Bn * N2];
__device__ float g_sh[Bn * Sn * Dn];
__device__ float g_sc[Bn * Sn * Dn];
__device__ float g_trkc[Bn * TDn];
__device__ int g_bufpos[Tn * Bn];
__device__ int g_p1[Tn * Bn];
__device__ int g_p2[Tn * Bn];
__device__ int g_wpos[Tn * Bn];
__device__ int g_op[Tn * Bn];
__device__ int g_fpos[Bn];

// ---------------- helpers ----------------
__device__ __forceinline__ float to_tf32(float x) {
    uint32_t y;
    asm("cvt.rna.tf32.f32 %0, %1;" : "=r"(y) : "f"(x));
    return __uint_as_float(y);
}
__device__ __forceinline__ float sigm(float x) { return 1.f / (1.f + expf(-x)); }

// ---------------- prologue: precompute shift/reduce indices ----------------
__global__ void idx_kernel(const int* __restrict__ tr) {
    int b = threadIdx.x;
    if (b >= Bn) return;
    int ptr = 0, buft = 0;
    for (int t = 0; t < Tn; t++) {
        int op = tr[b * Tn + t];
        int bp = Ln - 1 - buft;
        bp = bp < 0 ? 0 : (bp > Ln - 1 ? Ln - 1 : bp);
        g_bufpos[t * Bn + b] = bp;
        g_p1[t * Bn + b] = (ptr > 0) ? min(ptr - 1, Sn - 1) : -1;
        g_p2[t * Bn + b] = (ptr > 1) ? min(ptr - 2, Sn - 1) : -1;
        int wp = (op == 0) ? ptr : ptr - 2;
        wp = wp < 0 ? 0 : (wp > Sn - 1 ? Sn - 1 : wp);
        g_wpos[t * Bn + b] = wp;
        g_op[t * Bn + b] = op;
        ptr += (op == 0) ? 1 : ((op == 1) ? -1 : 0);
        buft += (op == 0) ? 1 : 0;
    }
    int fp = ptr - 1;
    fp = fp < 0 ? 0 : (fp > Sn - 1 ? Sn - 1 : fp);
    g_fpos[b] = fp;
}

// ---------------- prologue: concat + tf32-round weights ----------------
__global__ void conv_w(const float* __restrict__ Wbuf, const float* __restrict__ Ws1,
                       const float* __restrict__ Ws2, const float* __restrict__ Wlat,
                       const float* __restrict__ Wl, const float* __restrict__ Wr,
                       const float* __restrict__ Wt) {
    const int total1 = K1 * N1;
    const int total2 = K2 * N2;
    for (int i = blockIdx.x * blockDim.x + threadIdx.x; i < total1 + total2;
         i += gridDim.x * blockDim.x) {
        if (i < total1) {
            int k = i / N1, n = i - k * N1;
            const float* src = (k < 768) ? Wbuf : (k < 1536) ? Ws1 : (k < 2304) ? Ws2 : Wlat;
            g_W1[i] = to_tf32(src[(k % 768) * N1 + n]);
        } else {
            int j = i - total1;
            int k = j / N2, n = j - k * N2;
            const float* src = (k < 768) ? Wl : (k < 1536) ? Wr : Wt;
            g_W2[j] = to_tf32(src[(k % 768) * N2 + n]);
        }
    }
}

// ---------------- prologue: zero state + build A1/A2 for step 0 ----------------
__global__ void init_kernel(const float* __restrict__ buffer_h) {
    const int n1 = Bn * Sn * Dn;
    const int n2 = 2 * n1;
    const int n3 = n2 + Bn * TDn;
    const int n4 = n3 + Bn * K1;
    const int n5 = n4 + Bn * K2;
    for (int i = blockIdx.x * blockDim.x + threadIdx.x; i < n5; i += gridDim.x * blockDim.x) {
        if (i < n1) g_sh[i] = 0.f;
        else if (i < n2) g_sc[i - n1] = 0.f;
        else if (i < n3) g_trkc[i - n2] = 0.f;
        else if (i < n4) {
            int j = i - n3;
            int b = j / K1, k = j - b * K1;
            g_A1[j] = (k < 768) ? to_tf32(buffer_h[b * Ln * Dn + (Ln - 1) * Dn + k]) : 0.f;
        } else {
            g_A2[i - n4] = 0.f;
        }
    }
}

// ---------------- split-K TF32 GEMM: C[ky][64][N] = A[64, KS] @ W[KS, N] ----------------
// block tile 64(M) x 128(N) x 32(K); 8 warps = 2(m) x 4(n), warp tile 32x32
#define BM 64
#define BN 128
#define BK 32
#define A_ST 36   // A smem stride (BK + 4 pad)
#define W_ST 132  // W smem stride (BN + 4 pad)
#define ASZ (BM * A_ST)         // 2304 floats
#define WSZ (BK * W_ST)         // 4224 floats
#define STG_FLT (ASZ + WSZ)     // 6528 floats / stage
#define NSTAGE 4

__device__ __forceinline__ void cp16(uint32_t dst, const void* src) {
    asm volatile("cp.async.cg.shared.global [%0], [%1], 16;" :: "r"(dst), "l"(src));
}

__device__ __forceinline__ void prefetch_stage(float* stg, const float* A, const float* W,
                                               int ldA, int N, int kb, int n0, int tid) {
    // A tile: 64 x 32 floats = 512 cp16 (2 per thread)
#pragma unroll
    for (int j = 0; j < 2; j++) {
        int idx = tid + j * 256;
        int r = idx >> 3;            // /8 -> 0..63
        int c = (idx & 7) << 2;      // 0..28
        cp16((uint32_t)__cvta_generic_to_shared(stg + r * A_ST + c), A + r * ldA + kb + c);
    }
    // W tile: 32 x 128 floats = 1024 cp16 (4 per thread)
    float* ws = stg + ASZ;
#pragma unroll
    for (int j = 0; j < 4; j++) {
        int idx = tid + j * 256;
        int r = idx >> 5;            // /32 -> 0..31
        int c = (idx & 31) << 2;     // 0..124
        cp16((uint32_t)__cvta_generic_to_shared(ws + r * W_ST + c), W + (size_t)(kb + r) * N + n0 + c);
    }
}

__global__ void __launch_bounds__(256, 2) gemm_tf32(int which) {
    const float* A;
    const float* W;
    float* C;
    int ldA, N, KS;
    if (which == 1) { A = g_A1; W = g_W1; C = g_C1; ldA = K1; N = N1; KS = KS1; }
    else            { A = g_A2; W = g_W2; C = g_C2; ldA = K2; N = N2; KS = KS2; }

    extern __shared__ float sm[];

    const int tid = threadIdx.x;
    const int n0 = blockIdx.x * BN;
    const int kbase0 = blockIdx.y * KS;
    const int niter = KS / BK;   // 8

    const int lane = tid & 31, w = tid >> 5;
    const int wm = w >> 2, wn = w & 3;      // 2 x 4 warp grid
    const int g = lane >> 2, tg = lane & 3;

    float acc[2][4][4];
#pragma unroll
    for (int mt = 0; mt < 2; mt++)
#pragma unroll
        for (int nt = 0; nt < 4; nt++)
#pragma unroll
            for (int j = 0; j < 4; j++) acc[mt][nt][j] = 0.f;

    // prologue: issue stages 0..NSTAGE-2
#pragma unroll
    for (int s = 0; s < NSTAGE - 1; s++) {
        prefetch_stage(sm + s * STG_FLT, A, W, ldA, N, kbase0 + s * BK, n0, tid);
        asm volatile("cp.async.commit_group;");
    }

    for (int it = 0; it < niter; ++it) {
        asm volatile("cp.async.wait_group %0;" :: "n"(NSTAGE - 2));
        __syncthreads();

        // prefetch stage it+NSTAGE-1 into the slot freed by stage it-1
        if (it + NSTAGE - 1 < niter) {
            int s = (it + NSTAGE - 1) % NSTAGE;
            prefetch_stage(sm + s * STG_FLT, A, W, ldA, N, kbase0 + (it + NSTAGE - 1) * BK, n0, tid);
        }
        asm volatile("cp.async.commit_group;");

        const float* as = sm + (it % NSTAGE) * STG_FLT + (wm * 32) * A_ST;
        const float* ws = sm + (it % NSTAGE) * STG_FLT + ASZ + wn * 32;
#pragma unroll
        for (int ks = 0; ks < 4; ks++) {
            int kk = ks * 8;
            uint32_t a[2][4];
#pragma unroll
            for (int mt = 0; mt < 2; mt++) {
                const float* ar = as + (mt * 16) * A_ST;
                a[mt][0] = __float_as_uint(ar[g * A_ST + kk + tg]);
                a[mt][1] = __float_as_uint(ar[(g + 8) * A_ST + kk + tg]);
                a[mt][2] = __float_as_uint(ar[g * A_ST + kk + tg + 4]);
                a[mt][3] = __float_as_uint(ar[(g + 8) * A_ST + kk + tg + 4]);
            }
            uint32_t bfr[4][2];
#pragma unroll
            for (int nt = 0; nt < 4; nt++) {
                bfr[nt][0] = __float_as_uint(ws[(kk + tg) * W_ST + nt * 8 + g]);
                bfr[nt][1] = __float_as_uint(ws[(kk + tg + 4) * W_ST + nt * 8 + g]);
            }
#pragma unroll
            for (int mt = 0; mt < 2; mt++)
#pragma unroll
                for (int nt = 0; nt < 4; nt++) {
                    asm volatile(
                        "mma.sync.aligned.m16n8k8.row.col.f32.tf32.tf32.f32 "
                        "{%0,%1,%2,%3}, {%4,%5,%6,%7}, {%8,%9}, {%0,%1,%2,%3};"
                        : "+f"(acc[mt][nt][0]), "+f"(acc[mt][nt][1]),
                          "+f"(acc[mt][nt][2]), "+f"(acc[mt][nt][3])
                        : "r"(a[mt][0]), "r"(a[mt][1]), "r"(a[mt][2]), "r"(a[mt][3]),
                          "r"(bfr[nt][0]), "r"(bfr[nt][1]));
                }
        }
    }

    // epilogue: write split-K partial
    float* Cp = C + (size_t)blockIdx.y * (Bn * N) + n0;
#pragma unroll
    for (int mt = 0; mt < 2; mt++) {
        int row0 = wm * 32 + mt * 16 + g;
#pragma unroll
        for (int nt = 0; nt < 4; nt++) {
            int col = wn * 32 + nt * 8 + tg * 2;
            *(float2*)(Cp + (size_t)row0 * N + col) = make_float2(acc[mt][nt][0], acc[mt][nt][1]);
            *(float2*)(Cp + (size_t)(row0 + 8) * N + col) = make_float2(acc[mt][nt][2], acc[mt][nt][3]);
        }
    }
}

// ---------------- per-step: tracker LSTM update + logits ----------------
__global__ void tracker_kernel(int t, const float* __restrict__ b_lat,
                               const float* __restrict__ Wtr, const float* __restrict__ btr,
                               float* __restrict__ out) {
    int b = blockIdx.x;
    int d = threadIdx.x;
    float a = b_lat[d], ii = b_lat[d + 768], ff = b_lat[d + 1536], oo = b_lat[d + 2304];
#pragma unroll
    for (int p = 0; p < KSPL1; p++) {
        const float* cp = g_C1 + (size_t)p * Bn * N1 + (size_t)b * N1;
        a  += cp[d];
        ii += cp[d + 768];
        ff += cp[d + 1536];
        oo += cp[d + 2304];
    }
    float c = tanhf(a) * sigm(ii) + sigm(ff) * g_trkc[b * TDn + d];
    float h = sigm(oo) * tanhf(c);
    g_trkc[b * TDn + d] = c;
    float hr = to_tf32(h);
    g_A2[b * K2 + 1536 + d] = hr;
    g_A1[b * K1 + 2304 + d] = hr;

    float l0 = h * Wtr[d * 2];
    float l1 = h * Wtr[d * 2 + 1];
#pragma unroll
    for (int off = 16; off; off >>= 1) {
        l0 += __shfl_down_sync(0xffffffffu, l0, off);
        l1 += __shfl_down_sync(0xffffffffu, l1, off);
    }
    __shared__ float red[24][2];
    int wid = d >> 5;
    if ((d & 31) == 0) { red[wid][0] = l0; red[wid][1] = l1; }
    __syncthreads();
    if (d < 32) {
        float r0 = (d < 24) ? red[d][0] : 0.f;
        float r1 = (d < 24) ? red[d][1] : 0.f;
#pragma unroll
        for (int off = 16; off; off >>= 1) {
            r0 += __shfl_down_sync(0xffffffffu, r0, off);
            r1 += __shfl_down_sync(0xffffffffu, r1, off);
        }
        if (d == 0) {
            out[(size_t)b * OUTW + Dn + 2 * t]     = r0 + btr[0];
            out[(size_t)b * OUTW + Dn + 2 * t + 1] = r1 + btr[1];
        }
    }
}

// ---------------- per-step: compose + stack update + next-step gather ----------------
__global__ void compose_kernel(int t, const float* __restrict__ buffer_h,
                               const float* __restrict__ buffer_c,
                               const float* __restrict__ b_left) {
    int b = blockIdx.x;
    int d = threadIdx.x;
    int base = t * Bn + b;
    int p1 = g_p1[base], p2 = g_p2[base], wp = g_wpos[base], op = g_op[base], bp = g_bufpos[base];

    float s1c = (p1 >= 0) ? g_sc[(b * Sn + p1) * Dn + d] : 0.f;
    float s2c = (p2 >= 0) ? g_sc[(b * Sn + p2) * Dn + d] : 0.f;

    float gi = b_left[d], gfl = b_left[d + 768], gfr = b_left[d + 1536];
    float go = b_left[d + 2304], gg = b_left[d + 3072];
#pragma unroll
    for (int p = 0; p < KSPL2; p++) {
        const float* cp = g_C2 + (size_t)p * Bn * N2 + (size_t)b * N2;
        gi  += cp[d];
        gfl += cp[d + 768];
        gfr += cp[d + 1536];
        go  += cp[d + 2304];
        gg  += cp[d + 3072];
    }

    float cc = sigm(gfl) * s2c + sigm(gfr) * s1c + sigm(gi) * tanhf(gg);
    float ch = sigm(go) * tanhf(cc);

    float wh, wc;
    if (op == 0) {
        wh = buffer_h[(b * Ln + bp) * Dn + d];
        wc = buffer_c[(b * Ln + bp) * Dn + d];
    } else if (op == 1) {
        wh = ch; wc = cc;
    } else {
        wh = g_sh[(b * Sn + wp) * Dn + d];
        wc = g_sc[(b * Sn + wp) * Dn + d];
    }
    g_sh[(b * Sn + wp) * Dn + d] = wh;
    g_sc[(b * Sn + wp) * Dn + d] = wc;

    if (t + 1 < Tn) {
        int nb = (t + 1) * Bn + b;
        int nbp = g_bufpos[nb], np1 = g_p1[nb], np2 = g_p2[nb];
        float nbh = to_tf32(buffer_h[(b * Ln + nbp) * Dn + d]);
        float ns1 = (np1 >= 0) ? to_tf32(g_sh[(b * Sn + np1) * Dn + d]) : 0.f;
        float ns2 = (np2 >= 0) ? to_tf32(g_sh[(b * Sn + np2) * Dn + d]) : 0.f;
        g_A1[b * K1 + d] = nbh;
        g_A1[b * K1 + 768 + d] = ns1;
        g_A1[b * K1 + 1536 + d] = ns2;
        g_A2[b * K2 + d] = ns2;
        g_A2[b * K2 + 768 + d] = ns1;
    }
}

// ---------------- epilogue: final_h ----------------
__global__ void final_kernel(float* __restrict__ out) {
    int b = blockIdx.x, d = threadIdx.x;
    out[(size_t)b * OUTW + d] = g_sh[(b * Sn + g_fpos[b]) * Dn + d];
}

// ---------------- launch ----------------
extern "C" void kernel_launch(void* const* d_in, const int* in_sizes, int n_in,
                              void* d_out, int out_size) {
    const float* buffer_h = (const float*)d_in[0];
    const float* buffer_c = (const float*)d_in[1];
    const int* transitions = (const int*)d_in[2];
    const float* W_buf  = (const float*)d_in[3];
    const float* W_s1   = (const float*)d_in[4];
    const float* W_s2   = (const float*)d_in[5];
    const float* W_lat  = (const float*)d_in[6];
    const float* b_lat  = (const float*)d_in[7];
    const float* W_trans = (const float*)d_in[8];
    const float* b_trans = (const float*)d_in[9];
    const float* W_left = (const float*)d_in[10];
    const float* b_left = (const float*)d_in[11];
    const float* W_right = (const float*)d_in[12];
    const float* W_track = (const float*)d_in[13];
    float* out = (float*)d_out;

    const size_t smem = (size_t)NSTAGE * STG_FLT * sizeof(float); // 104448 B
    cudaFuncSetAttribute(gemm_tf32, cudaFuncAttributeMaxDynamicSharedMemorySize, (int)smem);

    conv_w<<<1024, 256>>>(W_buf, W_s1, W_s2, W_lat, W_left, W_right, W_track);
    idx_kernel<<<1, 64>>>(transitions);
    init_kernel<<<512, 256>>>(buffer_h);

    for (int t = 0; t < Tn; t++) {
        gemm_tf32<<<dim3(N1 / BN, KSPL1), 256, smem>>>(1);
        tracker_kernel<<<Bn, Dn>>>(t, b_lat, W_trans, b_trans, out);
        gemm_tf32<<<dim3(N2 / BN, KSPL2), 256, smem>>>(2);
        compose_kernel<<<Bn, Dn>>>(t, buffer_h, buffer_c, b_left);
    }
    final_kernel<<<Bn, Dn>>>(out);
}